// round 8
// baseline (speedup 1.0000x reference)
#include <cuda_runtime.h>
#include <math.h>
#include <stdint.h>

#define LQ 8192
#define HD 1024
#define PD 1024
#define N1 2048
#define NCHUNK 128
#define CHUNK 64

// ---- GEMM tile config ----
#define BM 128
#define BN 256
#define BK 32
#define NST 3
#define ASTR 40                          // smem row stride (floats): 8 mod 32 -> conflict-free lds.64
#define ASTG_F (128 * ASTR)              // A floats per stage (5120)
#define STGF (ASTG_F + 256 * ASTR)       // floats per stage (15360)
#define SMEM_BYTES (NST * STGF * 4)      // 184320

// ---------------- device scratch ----------------
__device__ float g_xt[LQ * HD];          // x, tf32-rounded, k-permuted
__device__ float g_Bbar[N1 * HD];        // (2P,H) tf32-rounded, k-permuted (H axis)
__device__ float g_Cf[HD * N1];          // (H,2P) tf32-rounded, k-permuted (2P axis)
__device__ float g_Bu[LQ * N1];          // fp32 scan input (natural order)
__device__ float g_xs[LQ * N1];          // scan output, tf32-rounded, k-permuted (2P axis)
__device__ float g_Abar_re[PD], g_Abar_im[PD];
__device__ float g_coef_re[PD], g_coef_im[PD];
__device__ float g_AS_re[PD],   g_AS_im[PD];
__device__ float g_E_re[NCHUNK * PD], g_E_im[NCHUNK * PD];
__device__ float g_pref_re[NCHUNK * PD], g_pref_im[NCHUNK * PD];

// ---------------- helpers ----------------
// k-permutation within each 8-group: t -> 2t, t+4 -> 2t+1 (self-consistent on both operands)
__device__ __forceinline__ int kperm(int idx) {
    int j = idx & 7;
    return (idx & ~7) | ((j & 3) << 1) | (j >> 2);
}
__device__ __forceinline__ float tf32r(float v) {
    uint32_t r;
    asm("cvt.rna.tf32.f32 %0, %1;" : "=r"(r) : "f"(v));
    return __uint_as_float(r);
}
__device__ __forceinline__ uint32_t smem_u32(const void* p) {
    uint32_t a;
    asm("{ .reg .u64 t; cvta.to.shared.u64 t, %1; cvt.u32.u64 %0, t; }" : "=r"(a) : "l"(p));
    return a;
}
__device__ __forceinline__ void cp16(uint32_t saddr, const void* gptr) {
    asm volatile("cp.async.ca.shared.global [%0], [%1], 16;" :: "r"(saddr), "l"(gptr));
}
#define CP_COMMIT() asm volatile("cp.async.commit_group;" ::: "memory")
#define CP_WAIT1()  asm volatile("cp.async.wait_group 1;" ::: "memory")

__device__ __forceinline__ void mma_tf32(float* c, uint32_t a0, uint32_t a1, uint32_t a2, uint32_t a3,
                                         uint32_t b0, uint32_t b1) {
    asm volatile("mma.sync.aligned.m16n8k8.row.col.f32.tf32.tf32.f32 "
        "{%0,%1,%2,%3}, {%4,%5,%6,%7}, {%8,%9}, {%0,%1,%2,%3};"
        : "+f"(c[0]), "+f"(c[1]), "+f"(c[2]), "+f"(c[3])
        : "r"(a0), "r"(a1), "r"(a2), "r"(a3), "r"(b0), "r"(b1));
}

// frag load: AF[i][0]={a0,a2}@row(i*16+g), AF[i][1]={a1,a3}@row+8; BF[j]={b0,b1}@row(j*8+g)
#define LDFRAG(AF, BF, stp, kk) do {                                             \
    const float* _pa = (stp) + (warp_m + g) * ASTR + t * 2 + (kk) * 8;           \
    const float* _pb = (stp) + ASTG_F + (warp_n + g) * ASTR + t * 2 + (kk) * 8;  \
    AF[0][0] = *(const float2*)(_pa);        AF[0][1] = *(const float2*)(_pa + 320);  \
    AF[1][0] = *(const float2*)(_pa + 640);  AF[1][1] = *(const float2*)(_pa + 960);  \
    AF[2][0] = *(const float2*)(_pa + 1280); AF[2][1] = *(const float2*)(_pa + 1600); \
    AF[3][0] = *(const float2*)(_pa + 1920); AF[3][1] = *(const float2*)(_pa + 2240); \
    BF[0] = *(const float2*)(_pb);        BF[1] = *(const float2*)(_pb + 320);   \
    BF[2] = *(const float2*)(_pb + 640);  BF[3] = *(const float2*)(_pb + 960);   \
    BF[4] = *(const float2*)(_pb + 1280); BF[5] = *(const float2*)(_pb + 1600);  \
    BF[6] = *(const float2*)(_pb + 1920); BF[7] = *(const float2*)(_pb + 2240);  \
} while (0)

#define DO_MMA(AF, BF) do {                                                      \
    _Pragma("unroll")                                                            \
    for (int _i = 0; _i < 4; _i++) {                                             \
        uint32_t _a0 = __float_as_uint(AF[_i][0].x), _a1 = __float_as_uint(AF[_i][1].x); \
        uint32_t _a2 = __float_as_uint(AF[_i][0].y), _a3 = __float_as_uint(AF[_i][1].y); \
        _Pragma("unroll")                                                        \
        for (int _j = 0; _j < 8; _j++)                                           \
            mma_tf32(acc[_i][_j], _a0, _a1, _a2, _a3,                            \
                     __float_as_uint(BF[_j].x), __float_as_uint(BF[_j].y));      \
    }                                                                            \
} while (0)

// ---------------- setup: discretization (fp64) ----------------
__global__ void setup_kernel(const float* __restrict__ Lre, const float* __restrict__ Lim,
                             const float* __restrict__ logdt)
{
    int p = blockIdx.x * blockDim.x + threadIdx.x;
    if (p >= PD) return;
    double dt  = exp((double)logdt[p]);
    double lr  = (double)Lre[p], li = (double)Lim[p];
    double mag = exp(lr * dt);
    double ang = li * dt;
    double ar  = mag * cos(ang);
    double ai  = mag * sin(ang);
    double den = lr * lr + li * li;
    double cr  = ((ar - 1.0) * lr + ai * li) / den;
    double ci  = (ai * lr - (ar - 1.0) * li) / den;
    g_Abar_re[p] = (float)ar; g_Abar_im[p] = (float)ai;
    g_coef_re[p] = (float)cr; g_coef_im[p] = (float)ci;
    double sr = ar, si = ai;
    #pragma unroll
    for (int i = 0; i < 6; i++) {
        double nr = sr * sr - si * si;
        double ni = 2.0 * sr * si;
        sr = nr; si = ni;
    }
    g_AS_re[p] = (float)sr; g_AS_im[p] = (float)si;
}

__global__ void conv_x(const float* __restrict__ x)
{
    int idx = blockIdx.x * blockDim.x + threadIdx.x;
    if (idx >= LQ * HD) return;
    g_xt[kperm(idx)] = tf32r(x[idx]);
}

__global__ void build_bbar(const float* __restrict__ Bre, const float* __restrict__ Bim)
{
    int idx = blockIdx.x * blockDim.x + threadIdx.x;
    if (idx >= PD * HD) return;
    int p = idx >> 10;
    float br = Bre[idx], bi = Bim[idx];
    float cr = g_coef_re[p], ci = g_coef_im[p];
    int pidx = kperm(idx);                       // permutes h (low bits)
    g_Bbar[pidx]           = tf32r(cr * br - ci * bi);
    g_Bbar[PD * HD + pidx] = tf32r(cr * bi + ci * br);
}

__global__ void build_cfused(const float* __restrict__ Cre, const float* __restrict__ Cim)
{
    int idx = blockIdx.x * blockDim.x + threadIdx.x;
    if (idx >= HD * PD) return;
    int h = idx >> 10, p = idx & (PD - 1);
    int q = kperm(p);
    g_Cf[h * N1 + q]      = tf32r( Cre[idx]);
    g_Cf[h * N1 + PD + q] = tf32r(-Cim[idx]);
}

// ---------------- mma.sync tf32 GEMM: C[M,CN] = A[M,K] @ B[N,K]^T ----------------
// BM=128, BN=256, BK=32, 3-stage cp.async, warp tile 64x64, lds.64 frags, reg double-buffer
template<int K, bool G1>
__global__ __launch_bounds__(256)
void gemm_mma(const float* __restrict__ A, float* __restrict__ Cout,
              const float* __restrict__ xres, const float* __restrict__ Dp)
{
    const float* B = G1 ? g_Bbar : g_Cf;
    float* C = G1 ? g_Bu : Cout;
    const int CN = G1 ? N1 : HD;

    extern __shared__ float sm[];
    const uint32_t sbase = smem_u32(sm);
    const int tid  = threadIdx.x;
    const int wid  = tid >> 5;
    const int lane = tid & 31;
    const int g = lane >> 2, t = lane & 3;
    const int warp_m = (wid & 1) * 64;
    const int warp_n = (wid >> 1) * 64;
    const int bm = blockIdx.y * BM;
    const int bn = blockIdx.x * BN;

    const int arow = tid >> 3;
    const int aq   = (tid & 7) * 4;
    const float* Ag = A + (size_t)(bm + arow) * K + aq;
    const float* Bg = B + (size_t)(bn + arow) * K + aq;
    const uint32_t sAo = (uint32_t)(arow * ASTR + aq) * 4;

    float acc[4][8][4];
    #pragma unroll
    for (int i = 0; i < 4; i++)
        #pragma unroll
        for (int j = 0; j < 8; j++)
            #pragma unroll
            for (int q = 0; q < 4; q++) acc[i][j][q] = 0.f;

    constexpr int NCH = K / BK;

    auto load_stage = [&](int st, int k0) {
        const uint32_t sa = sbase + (uint32_t)(st * STGF * 4) + sAo;
        const uint32_t sb = sa + (uint32_t)(ASTG_F * 4);
        #pragma unroll
        for (int i = 0; i < 4; i++)
            cp16(sa + i * 32 * ASTR * 4, Ag + k0 + (size_t)i * 32 * K);
        #pragma unroll
        for (int i = 0; i < 8; i++)
            cp16(sb + i * 32 * ASTR * 4, Bg + k0 + (size_t)i * 32 * K);
    };

    load_stage(0, 0);  CP_COMMIT();
    load_stage(1, BK); CP_COMMIT();
    CP_WAIT1();
    __syncthreads();

    float2 af0[4][2], af1[4][2], bf0[8], bf1[8];
    LDFRAG(af0, bf0, sm, 0);                     // stage 0, kk 0

    for (int kc = 0; kc < NCH; kc++) {
        const int st = kc % NST;
        const float* stp = sm + st * STGF;

        LDFRAG(af1, bf1, stp, 1);
        DO_MMA(af0, bf0);
        LDFRAG(af0, bf0, stp, 2);
        DO_MMA(af1, bf1);
        LDFRAG(af1, bf1, stp, 3);
        DO_MMA(af0, bf0);

        if (kc + 2 < NCH) load_stage((kc + 2) % NST, (kc + 2) * BK);
        CP_COMMIT();

        DO_MMA(af1, bf1);

        if (kc + 1 < NCH) {
            CP_WAIT1();
            __syncthreads();
            LDFRAG(af0, bf0, sm + ((kc + 1) % NST) * STGF, 0);
        }
    }

    // epilogue: c0,c1 at (row, col..col+1); c2,c3 at (row+8, ...)
    #pragma unroll
    for (int i = 0; i < 4; i++) {
        const int row = bm + warp_m + i * 16 + g;
        #pragma unroll
        for (int j = 0; j < 8; j++) {
            const int col = bn + warp_n + j * 8 + 2 * t;
            float* cp0 = C + (size_t)row * CN + col;
            float* cp1 = C + (size_t)(row + 8) * CN + col;
            if (!G1) {
                const float* xp0 = xres + (size_t)row * HD + col;
                const float* xp1 = xres + (size_t)(row + 8) * HD + col;
                float2 dv = *(const float2*)(Dp + col);
                float2 x0 = *(const float2*)xp0;
                float2 x1 = *(const float2*)xp1;
                float2 v0, v1;
                v0.x = 2.f * acc[i][j][0] + x0.x * (1.f + dv.x);
                v0.y = 2.f * acc[i][j][1] + x0.y * (1.f + dv.y);
                v1.x = 2.f * acc[i][j][2] + x1.x * (1.f + dv.x);
                v1.y = 2.f * acc[i][j][3] + x1.y * (1.f + dv.y);
                *(float2*)cp0 = v0;
                *(float2*)cp1 = v1;
            } else {
                *(float2*)cp0 = make_float2(acc[i][j][0], acc[i][j][1]);
                *(float2*)cp1 = make_float2(acc[i][j][2], acc[i][j][3]);
            }
        }
    }
}

// ---------------- chunked scan ----------------
__global__ __launch_bounds__(256) void scan_phase1()
{
    int p = blockIdx.y * blockDim.x + threadIdx.x;
    int c = blockIdx.x;
    float Ar = g_Abar_re[p], Ai = g_Abar_im[p];
    float hr = 0.f, hi = 0.f;
    const float* bu = g_Bu + (size_t)c * CHUNK * N1;
    #pragma unroll 4
    for (int i = 0; i < CHUNK; i++) {
        float br = bu[i * N1 + p];
        float bi = bu[i * N1 + PD + p];
        float nr = fmaf(Ar, hr, fmaf(-Ai, hi, br));
        float ni = fmaf(Ar, hi, fmaf(Ai, hr, bi));
        hr = nr; hi = ni;
    }
    g_E_re[c * PD + p] = hr;
    g_E_im[c * PD + p] = hi;
}

__global__ __launch_bounds__(256) void scan_phase2()
{
    int p = blockIdx.x * blockDim.x + threadIdx.x;
    float Ar = g_AS_re[p], Ai = g_AS_im[p];
    float pr = 0.f, pi = 0.f;
    for (int c = 0; c < NCHUNK; c++) {
        g_pref_re[c * PD + p] = pr;
        g_pref_im[c * PD + p] = pi;
        float er = g_E_re[c * PD + p], ei = g_E_im[c * PD + p];
        float nr = fmaf(Ar, pr, fmaf(-Ai, pi, er));
        float ni = fmaf(Ar, pi, fmaf(Ai, pr, ei));
        pr = nr; pi = ni;
    }
}

__global__ __launch_bounds__(256) void scan_phase3()
{
    int p = blockIdx.y * blockDim.x + threadIdx.x;
    int c = blockIdx.x;
    int q = kperm(p);                              // permuted column for GEMM2's K axis
    float Ar = g_Abar_re[p], Ai = g_Abar_im[p];
    float hr = g_pref_re[c * PD + p];
    float hi = g_pref_im[c * PD + p];
    const float* bu = g_Bu + (size_t)c * CHUNK * N1;
    float*       xs = g_xs + (size_t)c * CHUNK * N1;
    #pragma unroll 4
    for (int i = 0; i < CHUNK; i++) {
        float br = bu[i * N1 + p];
        float bi = bu[i * N1 + PD + p];
        float nr = fmaf(Ar, hr, fmaf(-Ai, hi, br));
        float ni = fmaf(Ar, hi, fmaf(Ai, hr, bi));
        hr = nr; hi = ni;
        xs[i * N1 + q]      = tf32r(hr);
        xs[i * N1 + PD + q] = tf32r(hi);
    }
}

// ---------------- LayerNorm (in place) ----------------
__global__ __launch_bounds__(256) void ln_kernel(float* __restrict__ out,
                                                 const float* __restrict__ gamma,
                                                 const float* __restrict__ beta)
{
    __shared__ float sh_s[8], sh_s2[8], sh_mr[2];
    int row = blockIdx.x;
    float* r = out + (size_t)row * HD;
    int tid = threadIdx.x;
    float v[4], s = 0.f, s2 = 0.f;
    #pragma unroll
    for (int k = 0; k < 4; k++) {
        v[k] = r[tid + k * 256];
        s += v[k];
        s2 = fmaf(v[k], v[k], s2);
    }
    #pragma unroll
    for (int o = 16; o > 0; o >>= 1) {
        s  += __shfl_down_sync(0xffffffffu, s,  o);
        s2 += __shfl_down_sync(0xffffffffu, s2, o);
    }
    if ((tid & 31) == 0) { sh_s[tid >> 5] = s; sh_s2[tid >> 5] = s2; }
    __syncthreads();
    if (tid == 0) {
        float ts = 0.f, ts2 = 0.f;
        #pragma unroll
        for (int w = 0; w < 8; w++) { ts += sh_s[w]; ts2 += sh_s2[w]; }
        float mean = ts * (1.f / HD);
        float var  = ts2 * (1.f / HD) - mean * mean;
        sh_mr[0] = mean;
        sh_mr[1] = rsqrtf(var + 1e-5f);
    }
    __syncthreads();
    float mean = sh_mr[0], rstd = sh_mr[1];
    #pragma unroll
    for (int k = 0; k < 4; k++) {
        int h = tid + k * 256;
        r[h] = (v[k] - mean) * rstd * gamma[h] + beta[h];
    }
}

// ---------------- launch ----------------
extern "C" void kernel_launch(void* const* d_in, const int* in_sizes, int n_in,
                              void* d_out, int out_size)
{
    const float* x     = (const float*)d_in[0];
    const float* Lre   = (const float*)d_in[1];
    const float* Lim   = (const float*)d_in[2];
    const float* Bre   = (const float*)d_in[3];
    const float* Bim   = (const float*)d_in[4];
    const float* Cre   = (const float*)d_in[5];
    const float* Cim   = (const float*)d_in[6];
    const float* D     = (const float*)d_in[7];
    const float* logdt = (const float*)d_in[8];
    const float* gamma = (const float*)d_in[9];
    const float* beta  = (const float*)d_in[10];
    float* out = (float*)d_out;

    cudaFuncSetAttribute(gemm_mma<HD, true>,  cudaFuncAttributeMaxDynamicSharedMemorySize, SMEM_BYTES);
    cudaFuncSetAttribute(gemm_mma<N1, false>, cudaFuncAttributeMaxDynamicSharedMemorySize, SMEM_BYTES);

    setup_kernel<<<4, 256>>>(Lre, Lim, logdt);
    conv_x<<<LQ * HD / 256, 256>>>(x);
    build_bbar<<<PD * HD / 256, 256>>>(Bre, Bim);
    build_cfused<<<HD * PD / 256, 256>>>(Cre, Cim);

    // Bu = x @ Bbar^T   (M=8192, N=2048, K=1024)
    float* xt_ptr = nullptr;
    cudaGetSymbolAddress((void**)&xt_ptr, g_xt);
    gemm_mma<HD, true><<<dim3(N1 / BN, LQ / BM), 256, SMEM_BYTES>>>(xt_ptr, nullptr, nullptr, nullptr);

    scan_phase1<<<dim3(NCHUNK, PD / 256), 256>>>();
    scan_phase2<<<PD / 256, 256>>>();
    scan_phase3<<<dim3(NCHUNK, PD / 256), 256>>>();

    // out = 2*Re(xs @ C^T) + x*(1+D)   (M=8192, N=1024, K=2048)
    float* xs_ptr = nullptr;
    cudaGetSymbolAddress((void**)&xs_ptr, g_xs);
    gemm_mma<N1, false><<<dim3(HD / BN, LQ / BM), 256, SMEM_BYTES>>>(xs_ptr, out, x, D);

    ln_kernel<<<LQ, 256>>>(out, gamma, beta);
}